// round 7
// baseline (speedup 1.0000x reference)
#include <cuda_runtime.h>
#include <math.h>

#define H 64
#define MAX_N 65536
#define CAP 64
#define MAX_OVF 65536

// Fused counter block: [0, MAX_N) = in-degree bin cursors (cnt),
// [MAX_N, 2*MAX_N) = out-degree, [2*MAX_N] = overflow counter (padded to 4).
// Zeroed + L2-warmed by k_zero at the head of every call.
#define META_INTS (2 * MAX_N + 4)
__device__ int   g_meta[META_INTS];
__device__ float g_f[MAX_N * H];        // feature * src_norm (+ zero row at n)
__device__ int   g_ebuf[MAX_N * CAP];   // dst-binned src indices
__device__ int2  g_ovf[MAX_OVF];        // overflow (dst, src) pairs

#define g_cnt    (g_meta)
#define g_degout (g_meta + MAX_N)
#define g_ovfn   (g_meta + 2 * MAX_N)

// Zero + L2-warm all counters. int4 stores, one pass.
__global__ void k_zero() {
    int i = blockIdx.x * blockDim.x + threadIdx.x;
    if (i < META_INTS / 4)
        ((int4*)g_meta)[i] = make_int4(0, 0, 0, 0);
}

// One pass over edges: out-degree histogram + dst-binning. 2 edges/thread.
__global__ void k_bin(const int* __restrict__ src, const int* __restrict__ dst, int e) {
    int t = blockIdx.x * blockDim.x + threadIdx.x;
    int i = t * 2;
    if (i + 1 < e) {
        int2 s2 = *(const int2*)(src + i);
        int2 d2 = *(const int2*)(dst + i);
        atomicAdd(&g_degout[s2.x], 1);
        atomicAdd(&g_degout[s2.y], 1);
        int p0 = atomicAdd(&g_cnt[d2.x], 1);
        int p1 = atomicAdd(&g_cnt[d2.y], 1);
        if (p0 < CAP) g_ebuf[d2.x * CAP + p0] = s2.x;
        else { int k = atomicAdd(g_ovfn, 1); if (k < MAX_OVF) g_ovf[k] = make_int2(d2.x, s2.x); }
        if (p1 < CAP) g_ebuf[d2.y * CAP + p1] = s2.y;
        else { int k = atomicAdd(g_ovfn, 1); if (k < MAX_OVF) g_ovf[k] = make_int2(d2.y, s2.y); }
    } else if (i < e) {
        int s = src[i], d = dst[i];
        atomicAdd(&g_degout[s], 1);
        int p = atomicAdd(&g_cnt[d], 1);
        if (p < CAP) g_ebuf[d * CAP + p] = s;
        else { int k = atomicAdd(g_ovfn, 1); if (k < MAX_OVF) g_ovf[k] = make_int2(d, s); }
    }
}

// Prescale: g_f = feat * rsqrt(max(degout,1)).
__global__ void k_scale(const float* __restrict__ feat, int n) {
    int i = blockIdx.x * blockDim.x + threadIdx.x;
    if (i < n * H) {
        int node = i >> 6;
        float d = (float)g_degout[node];
        g_f[i] = feat[i] * rsqrtf(fmaxf(d, 1.f));
    }
}

// Fused gather-SpMM + epilogue. TWO nodes per warp (one per 16-lane half,
// float4 per lane). All bin indices are prefetched before the mainloop;
// every batch runs a fixed, fully-unrolled 16 iterations (padding lanes
// carry the zero row at index n, which contributes exactly 0).
__global__ void __launch_bounds__(256, 5)
k_gather(const float* __restrict__ feat,
         const float* __restrict__ hw,
         const float* __restrict__ hb,
         const int* __restrict__ niter_p,
         float* __restrict__ out, int n) {
    int gwarp = (blockIdx.x * blockDim.x + threadIdx.x) >> 5;
    int lane  = threadIdx.x & 31;
    int half  = lane >> 4;
    int hl    = lane & 15;
    int node  = gwarp * 2 + half;
    bool active = node < n;
    int nodec = active ? node : 0;
    unsigned hmask = half ? 0xFFFF0000u : 0x0000FFFFu;

    int deg  = active ? g_cnt[nodec] : 0;   // true in-degree
    int degb = min(deg, CAP);
    float dn = rsqrtf(fmaxf((float)deg, 1.f));

    // Uniform batch count across the warp's two halves.
    int degm = max(degb, __shfl_xor_sync(0xffffffffu, degb, 16));

    const int* bin = g_ebuf + nodec * CAP;

    // Prefetch indices for all (up to 4) batches; padding -> zero row n.
    int sb[4];
    #pragma unroll
    for (int b = 0; b < 4; b++) {
        int idx = b * 16 + hl;
        sb[b] = (idx < degb) ? bin[idx] : n;
    }

    const float4* F4 = (const float4*)g_f;
    float4 a0 = make_float4(0.f, 0.f, 0.f, 0.f);
    float4 a1 = make_float4(0.f, 0.f, 0.f, 0.f);
    float4 a2 = make_float4(0.f, 0.f, 0.f, 0.f);
    float4 a3 = make_float4(0.f, 0.f, 0.f, 0.f);

    #pragma unroll
    for (int b = 0; b < 4; b++) {
        if (degm > b * 16) {            // warp-uniform branch
            int s_l = sb[b];
            #pragma unroll
            for (int k = 0; k < 16; k += 4) {
                int s0 = __shfl_sync(0xffffffffu, s_l, k,     16);
                int s1 = __shfl_sync(0xffffffffu, s_l, k + 1, 16);
                int s2 = __shfl_sync(0xffffffffu, s_l, k + 2, 16);
                int s3 = __shfl_sync(0xffffffffu, s_l, k + 3, 16);
                float4 v0 = F4[(size_t)s0 * 16 + hl];
                float4 v1 = F4[(size_t)s1 * 16 + hl];
                float4 v2 = F4[(size_t)s2 * 16 + hl];
                float4 v3 = F4[(size_t)s3 * 16 + hl];
                a0.x += v0.x; a0.y += v0.y; a0.z += v0.z; a0.w += v0.w;
                a1.x += v1.x; a1.y += v1.y; a1.z += v1.z; a1.w += v1.w;
                a2.x += v2.x; a2.y += v2.y; a2.z += v2.z; a2.w += v2.w;
                a3.x += v3.x; a3.y += v3.y; a3.z += v3.z; a3.w += v3.w;
            }
        }
    }
    float4 acc;
    acc.x = (a0.x + a1.x) + (a2.x + a3.x);
    acc.y = (a0.y + a1.y) + (a2.y + a3.y);
    acc.z = (a0.z + a1.z) + (a2.z + a3.z);
    acc.w = (a0.w + a1.w) + (a2.w + a3.w);

    // Overflow edges (empty in practice; correct if not)
    if (deg > CAP) {
        int novf = min(*g_ovfn, MAX_OVF);
        for (int i = 0; i < novf; i++) {
            int2 pr = g_ovf[i];
            if (pr.x == node) {
                float4 v = F4[(size_t)pr.y * 16 + hl];
                acc.x += v.x; acc.y += v.y; acc.z += v.z; acc.w += v.w;
            }
        }
    }

    // prop = acc * dn; halting head
    float4 p;
    p.x = acc.x * dn; p.y = acc.y * dn; p.z = acc.z * dn; p.w = acc.w * dn;
    float4 w = ((const float4*)hw)[hl];
    float dot = w.x * p.x + w.y * p.y + w.z * p.z + w.w * p.w;
    #pragma unroll
    for (int o = 8; o > 0; o >>= 1)
        dot += __shfl_xor_sync(hmask, dot, o, 16);
    float z = dot + hb[0];
    float h = 1.f / (1.f + expf(-z));

    int niter = niter_p ? *niter_p : 10;
    float niter_f = (float)niter;

    // Exact emulation of the halting recurrence (prop/h loop-invariant, so
    // only iteration 0's p blends in `feature`; every later active iteration
    // contributes exactly `prop`). Verified bit-compatible R1-R6.
    float steps = 1.f, sum_h = 0.f;
    bool cont = true;
    float pfirst = 1.f;
    int U = 0;
    for (int t = 0; t < niter; ++t) {
        bool prob = (sum_h + h < 0.99f) && cont;
        if (cont) U++;
        float probf = prob ? 1.f : 0.f;
        steps += probf;
        sum_h += probf * h;
        bool condition = prob && (steps < niter_f);
        float pp = condition ? sum_h : 1.f - sum_h;
        if (t == 0) pfirst = pp;
        cont = cont && prob;
    }

    float cprop = pfirst + (float)(U - 1);
    float cfeat = 1.f - pfirst;

    if (active) {
        const float4* FT4 = (const float4*)feat;
        float4 f = FT4[(size_t)node * 16 + hl];
        float inv_steps = 1.f / steps;
        float4 r;
        r.x = (p.x * cprop + f.x * cfeat) * inv_steps;
        r.y = (p.y * cprop + f.y * cfeat) * inv_steps;
        r.z = (p.z * cprop + f.z * cfeat) * inv_steps;
        r.w = (p.w * cprop + f.w * cfeat) * inv_steps;
        ((float4*)out)[(size_t)node * 16 + hl] = r;
        if (hl == 0) {
            out[(size_t)n * H + node] = steps;            // steps
            out[(size_t)n * H + n + node] = 1.f - sum_h;  // remainder
        }
    }
}

extern "C" void kernel_launch(void* const* d_in, const int* in_sizes, int n_in,
                              void* d_out, int out_size) {
    const float* feat = (const float*)d_in[0];
    const int*   src  = (const int*)d_in[1];
    const int*   dst  = (const int*)d_in[2];
    const float* hw   = (const float*)d_in[3];
    const float* hb   = (const float*)d_in[4];
    const int*   nit  = (n_in >= 6) ? (const int*)d_in[5] : nullptr;

    int n = in_sizes[0] / H;
    int e = in_sizes[1];
    float* out = (float*)d_out;

    k_zero<<<(META_INTS / 4 + 255) / 256, 256>>>();
    k_bin<<<((e + 1) / 2 + 255) / 256, 256>>>(src, dst, e);
    k_scale<<<(n * H + 255) / 256, 256>>>(feat, n);
    {
        long long threads = (long long)((n + 1) / 2) * 32;
        int blocks = (int)((threads + 255) / 256);
        k_gather<<<blocks, 256>>>(feat, hw, hb, nit, out, n);
    }
}

// round 10
// speedup vs baseline: 1.0205x; 1.0205x over previous
#include <cuda_runtime.h>
#include <math.h>

#define H 64
#define MAX_N 65536
#define CAP 64
#define MAX_OVF 65536

// Fused counter block: [0, MAX_N) = in-degree bin cursors (cnt),
// [MAX_N, 2*MAX_N) = out-degree, [2*MAX_N] = overflow counter (padded to 4).
#define META_INTS (2 * MAX_N + 4)
__device__ int   g_meta[META_INTS];
__device__ float g_srcnorm[MAX_N];      // rsqrt(max(degout,1))
__device__ int   g_ebuf[MAX_N * CAP];   // dst-binned src indices
__device__ int2  g_ovf[MAX_OVF];        // overflow (dst, src) pairs

#define g_cnt    (g_meta)
#define g_degout (g_meta + MAX_N)
#define g_ovfn   (g_meta + 2 * MAX_N)

// Zero + L2-warm all counters. int4 stores, one pass.
__global__ void k_zero() {
    int i = blockIdx.x * blockDim.x + threadIdx.x;
    if (i < META_INTS / 4)
        ((int4*)g_meta)[i] = make_int4(0, 0, 0, 0);
}

// One pass over edges: out-degree histogram + dst-binning. 4 edges/thread
// (int4 loads, MLP=4 on the position atomics).
__global__ void k_bin(const int* __restrict__ src, const int* __restrict__ dst, int e) {
    int t = blockIdx.x * blockDim.x + threadIdx.x;
    int i = t * 4;
    if (i + 3 < e) {
        int4 s4 = *(const int4*)(src + i);
        int4 d4 = *(const int4*)(dst + i);
        atomicAdd(&g_degout[s4.x], 1);
        atomicAdd(&g_degout[s4.y], 1);
        atomicAdd(&g_degout[s4.z], 1);
        atomicAdd(&g_degout[s4.w], 1);
        int p0 = atomicAdd(&g_cnt[d4.x], 1);
        int p1 = atomicAdd(&g_cnt[d4.y], 1);
        int p2 = atomicAdd(&g_cnt[d4.z], 1);
        int p3 = atomicAdd(&g_cnt[d4.w], 1);
        if (p0 < CAP) g_ebuf[d4.x * CAP + p0] = s4.x;
        else { int k = atomicAdd(g_ovfn, 1); if (k < MAX_OVF) g_ovf[k] = make_int2(d4.x, s4.x); }
        if (p1 < CAP) g_ebuf[d4.y * CAP + p1] = s4.y;
        else { int k = atomicAdd(g_ovfn, 1); if (k < MAX_OVF) g_ovf[k] = make_int2(d4.y, s4.y); }
        if (p2 < CAP) g_ebuf[d4.z * CAP + p2] = s4.z;
        else { int k = atomicAdd(g_ovfn, 1); if (k < MAX_OVF) g_ovf[k] = make_int2(d4.z, s4.z); }
        if (p3 < CAP) g_ebuf[d4.w * CAP + p3] = s4.w;
        else { int k = atomicAdd(g_ovfn, 1); if (k < MAX_OVF) g_ovf[k] = make_int2(d4.w, s4.w); }
    } else {
        for (; i < e && i < t * 4 + 4; ++i) {
            int s = src[i], d = dst[i];
            atomicAdd(&g_degout[s], 1);
            int p = atomicAdd(&g_cnt[d], 1);
            if (p < CAP) g_ebuf[d * CAP + p] = s;
            else { int k = atomicAdd(g_ovfn, 1); if (k < MAX_OVF) g_ovf[k] = make_int2(d, s); }
        }
    }
}

// Tiny: srcnorm = rsqrt(max(degout,1)).
__global__ void k_norm(int n) {
    int i = blockIdx.x * blockDim.x + threadIdx.x;
    if (i < n) g_srcnorm[i] = rsqrtf(fmaxf((float)g_degout[i], 1.f));
}

// Fused gather-SpMM + epilogue. TWO nodes per warp (one per 16-lane half,
// float4 per lane). Bin indices AND src-norms prefetched before the mainloop;
// fixed fully-unrolled 16-iteration batches. Padding lanes carry sn=0, so
// their FFMA contribution is exactly 0 (s=0 row is L1-hot, safe to read).
__global__ void __launch_bounds__(256, 6)
k_gather(const float* __restrict__ feat,
         const float* __restrict__ hw,
         const float* __restrict__ hb,
         const int* __restrict__ niter_p,
         float* __restrict__ out, int n) {
    int gwarp = (blockIdx.x * blockDim.x + threadIdx.x) >> 5;
    int lane  = threadIdx.x & 31;
    int half  = lane >> 4;
    int hl    = lane & 15;
    int node  = gwarp * 2 + half;
    bool active = node < n;
    int nodec = active ? node : 0;
    unsigned hmask = half ? 0xFFFF0000u : 0x0000FFFFu;

    int deg  = active ? g_cnt[nodec] : 0;   // true in-degree
    int degb = min(deg, CAP);
    float dn = rsqrtf(fmaxf((float)deg, 1.f));

    // Uniform batch count across the warp's two halves.
    int degm = max(degb, __shfl_xor_sync(0xffffffffu, degb, 16));

    const int* bin = g_ebuf + nodec * CAP;

    // Prefetch indices + norms for all (up to 4) batches; padding -> s=0, sn=0.
    int   sb[4];
    float snb[4];
    #pragma unroll
    for (int b = 0; b < 4; b++) {
        int idx = b * 16 + hl;
        bool v = idx < degb;
        sb[b]  = v ? bin[idx] : 0;
        snb[b] = v ? g_srcnorm[sb[b]] : 0.f;
    }

    const float4* F4 = (const float4*)feat;
    float4 a0 = make_float4(0.f, 0.f, 0.f, 0.f);
    float4 a1 = make_float4(0.f, 0.f, 0.f, 0.f);

    #pragma unroll
    for (int b = 0; b < 4; b++) {
        if (degm > b * 16) {            // warp-uniform branch
            int   s_l  = sb[b];
            float sn_l = snb[b];
            #pragma unroll
            for (int k = 0; k < 16; k += 2) {
                int   s0 = __shfl_sync(0xffffffffu, s_l,  k,     16);
                int   s1 = __shfl_sync(0xffffffffu, s_l,  k + 1, 16);
                float n0 = __shfl_sync(0xffffffffu, sn_l, k,     16);
                float n1 = __shfl_sync(0xffffffffu, sn_l, k + 1, 16);
                float4 v0 = F4[(size_t)s0 * 16 + hl];
                float4 v1 = F4[(size_t)s1 * 16 + hl];
                a0.x += n0 * v0.x; a0.y += n0 * v0.y;
                a0.z += n0 * v0.z; a0.w += n0 * v0.w;
                a1.x += n1 * v1.x; a1.y += n1 * v1.y;
                a1.z += n1 * v1.z; a1.w += n1 * v1.w;
            }
        }
    }
    float4 acc;
    acc.x = a0.x + a1.x; acc.y = a0.y + a1.y;
    acc.z = a0.z + a1.z; acc.w = a0.w + a1.w;

    // Overflow edges (empty in practice; correct if not)
    if (deg > CAP) {
        int novf = min(*g_ovfn, MAX_OVF);
        for (int i = 0; i < novf; i++) {
            int2 pr = g_ovf[i];
            if (pr.x == node) {
                float sn = g_srcnorm[pr.y];
                float4 v = F4[(size_t)pr.y * 16 + hl];
                acc.x += sn * v.x; acc.y += sn * v.y;
                acc.z += sn * v.z; acc.w += sn * v.w;
            }
        }
    }

    // prop = acc * dn; halting head
    float4 p;
    p.x = acc.x * dn; p.y = acc.y * dn; p.z = acc.z * dn; p.w = acc.w * dn;
    float4 w = ((const float4*)hw)[hl];
    float dot = w.x * p.x + w.y * p.y + w.z * p.z + w.w * p.w;
    #pragma unroll
    for (int o = 8; o > 0; o >>= 1)
        dot += __shfl_xor_sync(hmask, dot, o, 16);
    float z = dot + hb[0];
    float h = 1.f / (1.f + expf(-z));

    int niter = niter_p ? *niter_p : 10;
    float niter_f = (float)niter;

    // Exact emulation of the halting recurrence (prop/h loop-invariant, so
    // only iteration 0's p blends in `feature`; every later active iteration
    // contributes exactly `prop`). Verified bit-compatible R1-R7.
    float steps = 1.f, sum_h = 0.f;
    bool cont = true;
    float pfirst = 1.f;
    int U = 0;
    for (int t = 0; t < niter; ++t) {
        bool prob = (sum_h + h < 0.99f) && cont;
        if (cont) U++;
        float probf = prob ? 1.f : 0.f;
        steps += probf;
        sum_h += probf * h;
        bool condition = prob && (steps < niter_f);
        float pp = condition ? sum_h : 1.f - sum_h;
        if (t == 0) pfirst = pp;
        cont = cont && prob;
    }

    float cprop = pfirst + (float)(U - 1);
    float cfeat = 1.f - pfirst;

    if (active) {
        float4 f = F4[(size_t)node * 16 + hl];
        float inv_steps = 1.f / steps;
        float4 r;
        r.x = (p.x * cprop + f.x * cfeat) * inv_steps;
        r.y = (p.y * cprop + f.y * cfeat) * inv_steps;
        r.z = (p.z * cprop + f.z * cfeat) * inv_steps;
        r.w = (p.w * cprop + f.w * cfeat) * inv_steps;
        ((float4*)out)[(size_t)node * 16 + hl] = r;
        if (hl == 0) {
            out[(size_t)n * H + node] = steps;            // steps
            out[(size_t)n * H + n + node] = 1.f - sum_h;  // remainder
        }
    }
}

extern "C" void kernel_launch(void* const* d_in, const int* in_sizes, int n_in,
                              void* d_out, int out_size) {
    const float* feat = (const float*)d_in[0];
    const int*   src  = (const int*)d_in[1];
    const int*   dst  = (const int*)d_in[2];
    const float* hw   = (const float*)d_in[3];
    const float* hb   = (const float*)d_in[4];
    const int*   nit  = (n_in >= 6) ? (const int*)d_in[5] : nullptr;

    int n = in_sizes[0] / H;
    int e = in_sizes[1];
    float* out = (float*)d_out;

    k_zero<<<(META_INTS / 4 + 255) / 256, 256>>>();
    k_bin<<<((e + 3) / 4 + 255) / 256, 256>>>(src, dst, e);
    k_norm<<<(n + 255) / 256, 256>>>(n);
    {
        long long threads = (long long)((n + 1) / 2) * 32;
        int blocks = (int)((threads + 255) / 256);
        k_gather<<<blocks, 256>>>(feat, hw, hb, nit, out, n);
    }
}